// round 9
// baseline (speedup 1.0000x reference)
#include <cuda_runtime.h>
#include <cuda_bf16.h>
#include <math.h>
#include <stdint.h>

// Problem constants
#define B_  4
#define L_  2048
#define D_  1024
#define H_  16
#define HD_ 64
#define M_TOT (B_ * L_)          // 8192 rows for all projection GEMMs

// ---------------------------------------------------------------------------
// Scratch (allocation-free rule: __device__ globals)
// ---------------------------------------------------------------------------
__device__ float g_Q[(size_t)M_TOT * D_];
__device__ float g_K[(size_t)M_TOT * D_];
__device__ float g_V[(size_t)M_TOT * D_];
__device__ float g_C[(size_t)M_TOT * D_];

// ---------------------------------------------------------------------------
// tf32 helpers
// ---------------------------------------------------------------------------
__device__ __forceinline__ float tf32r(float x) {   // round to tf32, as float
    uint32_t r;
    asm("cvt.rna.tf32.f32 %0, %1;" : "=r"(r) : "f"(x));
    return __uint_as_float(r);
}
__device__ __forceinline__ void mma_tf32(
    float& c0, float& c1, float& c2, float& c3,
    uint32_t a0, uint32_t a1, uint32_t a2, uint32_t a3,
    uint32_t b0, uint32_t b1)
{
    asm volatile(
        "mma.sync.aligned.m16n8k8.row.col.f32.tf32.tf32.f32 "
        "{%0,%1,%2,%3}, {%4,%5,%6,%7}, {%8,%9}, {%0,%1,%2,%3};\n"
        : "+f"(c0), "+f"(c1), "+f"(c2), "+f"(c3)
        : "r"(a0), "r"(a1), "r"(a2), "r"(a3), "r"(b0), "r"(b1));
}
// split x -> (hi, lo) as mma-ready uints
__device__ __forceinline__ void split2(float x, uint32_t& h, uint32_t& l) {
    float hf = tf32r(x);
    h = __float_as_uint(hf);
    l = __float_as_uint(tf32r(x - hf));
}

// ---------------------------------------------------------------------------
// GEMM on tensor cores, split-tf32 (hh + hl + lh), fp32-level accuracy.
// NEW: A/W staged in SMEM as plain fp32; hi/lo computed at fragment load.
// Halves SMEM bytes (fragments + staging); dynamic SMEM 40960 B (2 buf).
//   C[m][n] = sum_k A[m][k] * W[n][k] + bias[n]
// CTA tile 128x128, BK=16; 256 threads = 8 warps (warp_m 0..1 x warp_n 0..3),
// warp tile 64x32 via 4x4 m16n8k8 MMAs, 3 MMAs per tile (split).
// Fragment LDS banks: 20*g + tig (+k) all-distinct -> conflict-free.
// ---------------------------------------------------------------------------
#define TST 20                    // SMEM row stride in floats (16 + 4 pad)
#define GBUF (128 * TST)          // floats per stage per matrix = 2560

__global__ __launch_bounds__(256, 2) void gemm_tf32s_bias(
    const float* __restrict__ A, const float* __restrict__ W,
    const float* __restrict__ bias, float* __restrict__ C,
    int M, int N, int K)
{
    extern __shared__ float dsm[];
    float* Afp = dsm;                 // [2][GBUF] fp32
    float* Wfp = dsm + 2 * GBUF;      // [2][GBUF] fp32

    const int tid    = threadIdx.x;
    const int warp   = tid >> 5;
    const int lane   = tid & 31;
    const int g      = lane >> 2;    // 0..7
    const int tig    = lane & 3;     // 0..3
    const int warp_m = warp >> 2;    // 0..1 -> 64-row slab
    const int warp_n = warp & 3;     // 0..3 -> 32-col slab

    const int m0 = blockIdx.y * 128;
    const int n0 = blockIdx.x * 128;

    // Staging coords: 512 float4 per matrix per tile, 2 per thread
    const int lrow0 = tid >> 2;            // 0..63
    const int lrow1 = lrow0 + 64;          // 64..127
    const int lkq   = (tid & 3) << 2;      // 0,4,8,12

    const float* Ar0 = A + (size_t)(m0 + lrow0) * K + lkq;
    const float* Ar1 = A + (size_t)(m0 + lrow1) * K + lkq;
    const float* Wr0 = W + (size_t)(n0 + lrow0) * K + lkq;
    const float* Wr1 = W + (size_t)(n0 + lrow1) * K + lkq;

    float c[4][4][4];
#pragma unroll
    for (int i = 0; i < 4; i++)
#pragma unroll
        for (int j = 0; j < 4; j++)
#pragma unroll
            for (int r = 0; r < 4; r++) c[i][j][r] = 0.0f;

    // Prologue: stage tile 0 (plain float4 copies)
    {
        *(float4*)&Afp[lrow0 * TST + lkq] = *(const float4*)(Ar0);
        *(float4*)&Afp[lrow1 * TST + lkq] = *(const float4*)(Ar1);
        *(float4*)&Wfp[lrow0 * TST + lkq] = *(const float4*)(Wr0);
        *(float4*)&Wfp[lrow1 * TST + lkq] = *(const float4*)(Wr1);
    }
    __syncthreads();

    const int NT = K / 16;   // 64 tiles
    for (int kt = 0; kt < NT; kt++) {
        const int cur = kt & 1;
        const bool have_next = (kt + 1 < NT);

        float4 na0, na1, nw0, nw1;
        if (have_next) {
            const int kb = (kt + 1) * 16;
            na0 = *(const float4*)(Ar0 + kb);
            na1 = *(const float4*)(Ar1 + kb);
            nw0 = *(const float4*)(Wr0 + kb);
            nw1 = *(const float4*)(Wr1 + kb);
        }

        // Two k-steps of 8; split fragments at load
#pragma unroll
        for (int ks = 0; ks < 2; ks++) {
            const int k = ks * 8;
            uint32_t ah[4][4], al[4][4];
#pragma unroll
            for (int mt = 0; mt < 4; mt++) {
                const int r = warp_m * 64 + mt * 16 + g;
                const int ba = cur * GBUF + r * TST + k + tig;
                split2(Afp[ba],               ah[mt][0], al[mt][0]);
                split2(Afp[ba + 8 * TST],     ah[mt][1], al[mt][1]);
                split2(Afp[ba + 4],           ah[mt][2], al[mt][2]);
                split2(Afp[ba + 8 * TST + 4], ah[mt][3], al[mt][3]);
            }
#pragma unroll
            for (int nt = 0; nt < 4; nt++) {
                const int n = warp_n * 32 + nt * 8 + g;
                const int bb = cur * GBUF + n * TST + k + tig;
                uint32_t bh0, bl0, bh1, bl1;
                split2(Wfp[bb],     bh0, bl0);
                split2(Wfp[bb + 4], bh1, bl1);
#pragma unroll
                for (int mt = 0; mt < 4; mt++) {
                    mma_tf32(c[mt][nt][0], c[mt][nt][1], c[mt][nt][2], c[mt][nt][3],
                             ah[mt][0], ah[mt][1], ah[mt][2], ah[mt][3], bh0, bh1);
                    mma_tf32(c[mt][nt][0], c[mt][nt][1], c[mt][nt][2], c[mt][nt][3],
                             ah[mt][0], ah[mt][1], ah[mt][2], ah[mt][3], bl0, bl1);
                    mma_tf32(c[mt][nt][0], c[mt][nt][1], c[mt][nt][2], c[mt][nt][3],
                             al[mt][0], al[mt][1], al[mt][2], al[mt][3], bh0, bh1);
                }
            }
        }

        if (have_next) {
            const int nb = 1 - cur;
            *(float4*)&Afp[nb * GBUF + lrow0 * TST + lkq] = na0;
            *(float4*)&Afp[nb * GBUF + lrow1 * TST + lkq] = na1;
            *(float4*)&Wfp[nb * GBUF + lrow0 * TST + lkq] = nw0;
            *(float4*)&Wfp[nb * GBUF + lrow1 * TST + lkq] = nw1;
            __syncthreads();
        }
    }

    // Epilogue: bias add + float2 stores (audited mapping)
#pragma unroll
    for (int nt = 0; nt < 4; nt++) {
        const int col = n0 + warp_n * 32 + nt * 8 + 2 * tig;
        const float b0v = bias[col];
        const float b1v = bias[col + 1];
#pragma unroll
        for (int mt = 0; mt < 4; mt++) {
            const int row = m0 + warp_m * 64 + mt * 16 + g;
            *(float2*)(C + (size_t)row * N + col) =
                make_float2(c[mt][nt][0] + b0v, c[mt][nt][1] + b1v);
            *(float2*)(C + (size_t)(row + 8) * N + col) =
                make_float2(c[mt][nt][2] + b0v, c[mt][nt][3] + b1v);
        }
    }
}

// ---------------------------------------------------------------------------
// Flash attention, split-tf32 mma.sync. NEW: Q/K/V staged fp32 (no pre-split);
// hi/lo at fragment load. SMEM 105KB -> 52KB => 3 CTAs/SM. P aliases Ks.
// Arithmetic identical to the measured round-6/8 kernel.
// ---------------------------------------------------------------------------
#define AST 68
#define ATILE 4352          // 64*68

__global__ __launch_bounds__(256, 3) void attn_tc(
    const float* __restrict__ Q, const float* __restrict__ K,
    const float* __restrict__ V, float* __restrict__ O)
{
    extern __shared__ float sm[];
    float* Qs = sm;                  // fp32, pre-scaled by 1/8
    float* Ks = sm + ATILE;          // fp32; aliased as P after S-phase
    float* Vs = sm + 2 * ATILE;      // fp32
    float* Pbuf = Ks;
    float* maxbuf = sm + 3 * ATILE;  // [2][64]
    float* sumbuf = maxbuf + 128;    // [2][64]

    const int tid  = threadIdx.x;
    const int warp = tid >> 5;
    const int lane = tid & 31;
    const int g    = lane >> 2;
    const int tig  = lane & 3;
    const int warp_m = warp >> 1;
    const int warp_n = warp & 1;
    const int m0 = warp_m * 16;
    const int nb = warp_n * 32;

    const int q0 = blockIdx.x * 64;
    const int bh = blockIdx.y;
    const int b  = bh / H_;
    const int h  = bh % H_;

    const float* Qb = Q + (size_t)b * L_ * D_ + h * HD_;
    const float* Kb = K + (size_t)b * L_ * D_ + h * HD_;
    const float* Vb = V + (size_t)b * L_ * D_ + h * HD_;

    // Stage Q once, scaled by 1/8 (exact), fp32
#pragma unroll
    for (int t = 0; t < 4; t++) {
        int idx = tid + t * 256;
        int row = idx >> 4;
        int d0  = (idx & 15) << 2;
        float4 v = *(const float4*)(Qb + (size_t)(q0 + row) * D_ + d0);
        v.x *= 0.125f; v.y *= 0.125f; v.z *= 0.125f; v.w *= 0.125f;
        *(float4*)&Qs[row * AST + d0] = v;
    }

    float mi0 = -INFINITY, mi1 = -INFINITY, li0 = 0.0f, li1 = 0.0f;
    float oacc[4][4];
#pragma unroll
    for (int nt = 0; nt < 4; nt++)
#pragma unroll
        for (int r = 0; r < 4; r++) oacc[nt][r] = 0.0f;

    for (int kv0 = 0; kv0 < L_; kv0 += 64) {
        __syncthreads();   // (A) prev PV fragment reads done

        // Stage K, V as fp32
#pragma unroll
        for (int t = 0; t < 4; t++) {
            int idx = tid + t * 256;
            int row = idx >> 4;
            int d0  = (idx & 15) << 2;
            *(float4*)&Ks[row * AST + d0] =
                *(const float4*)(Kb + (size_t)(kv0 + row) * D_ + d0);
            *(float4*)&Vs[row * AST + d0] =
                *(const float4*)(Vb + (size_t)(kv0 + row) * D_ + d0);
        }
        __syncthreads();   // (B) tiles staged

        // ---- S = Qs K^T (split at load: hh + hl + lh) ----
        float sacc[4][4];
#pragma unroll
        for (int nt = 0; nt < 4; nt++)
#pragma unroll
            for (int r = 0; r < 4; r++) sacc[nt][r] = 0.0f;

#pragma unroll
        for (int k8 = 0; k8 < 8; k8++) {
            const int kb = k8 * 8;
            const int ra = (m0 + g) * AST + kb + tig;
            const int rb = (m0 + g + 8) * AST + kb + tig;
            uint32_t ah0, ah1, ah2, ah3, al0, al1, al2, al3;
            split2(Qs[ra],     ah0, al0);
            split2(Qs[rb],     ah1, al1);
            split2(Qs[ra + 4], ah2, al2);
            split2(Qs[rb + 4], ah3, al3);
#pragma unroll
            for (int nt = 0; nt < 4; nt++) {
                const int rn = (nb + nt * 8 + g) * AST + kb + tig;
                uint32_t bh0, bl0, bh1, bl1;
                split2(Ks[rn],     bh0, bl0);
                split2(Ks[rn + 4], bh1, bl1);
                mma_tf32(sacc[nt][0], sacc[nt][1], sacc[nt][2], sacc[nt][3],
                         ah0, ah1, ah2, ah3, bh0, bh1);
                mma_tf32(sacc[nt][0], sacc[nt][1], sacc[nt][2], sacc[nt][3],
                         ah0, ah1, ah2, ah3, bl0, bl1);
                mma_tf32(sacc[nt][0], sacc[nt][1], sacc[nt][2], sacc[nt][3],
                         al0, al1, al2, al3, bh0, bh1);
            }
        }

        // ---- Online softmax across the two warp_n halves ----
        float mx0 = -INFINITY, mx1 = -INFINITY;
#pragma unroll
        for (int nt = 0; nt < 4; nt++) {
            mx0 = fmaxf(mx0, fmaxf(sacc[nt][0], sacc[nt][1]));
            mx1 = fmaxf(mx1, fmaxf(sacc[nt][2], sacc[nt][3]));
        }
        mx0 = fmaxf(mx0, __shfl_xor_sync(0xffffffffu, mx0, 1));
        mx0 = fmaxf(mx0, __shfl_xor_sync(0xffffffffu, mx0, 2));
        mx1 = fmaxf(mx1, __shfl_xor_sync(0xffffffffu, mx1, 1));
        mx1 = fmaxf(mx1, __shfl_xor_sync(0xffffffffu, mx1, 2));
        if (tig == 0) {
            maxbuf[warp_n * 64 + m0 + g]     = mx0;
            maxbuf[warp_n * 64 + m0 + g + 8] = mx1;
        }
        __syncthreads();   // (C) also: all S-phase Ks reads done

        const float mn0 = fmaxf(mi0, fmaxf(maxbuf[m0 + g], maxbuf[64 + m0 + g]));
        const float mn1 = fmaxf(mi1, fmaxf(maxbuf[m0 + g + 8], maxbuf[64 + m0 + g + 8]));
        const float sc0 = __expf(mi0 - mn0);
        const float sc1 = __expf(mi1 - mn1);
        mi0 = mn0; mi1 = mn1;

        float ps0 = 0.0f, ps1 = 0.0f;
#pragma unroll
        for (int nt = 0; nt < 4; nt++) {
            sacc[nt][0] = __expf(sacc[nt][0] - mn0);
            sacc[nt][1] = __expf(sacc[nt][1] - mn0);
            sacc[nt][2] = __expf(sacc[nt][2] - mn1);
            sacc[nt][3] = __expf(sacc[nt][3] - mn1);
            ps0 += sacc[nt][0] + sacc[nt][1];
            ps1 += sacc[nt][2] + sacc[nt][3];
        }
        ps0 += __shfl_xor_sync(0xffffffffu, ps0, 1);
        ps0 += __shfl_xor_sync(0xffffffffu, ps0, 2);
        ps1 += __shfl_xor_sync(0xffffffffu, ps1, 1);
        ps1 += __shfl_xor_sync(0xffffffffu, ps1, 2);
        if (tig == 0) {
            sumbuf[warp_n * 64 + m0 + g]     = ps0;
            sumbuf[warp_n * 64 + m0 + g + 8] = ps1;
        }

        // Write P (fp32) over Ks; rescale O accumulators
#pragma unroll
        for (int nt = 0; nt < 4; nt++) {
            const int pc = nb + nt * 8 + 2 * tig;
            *(float2*)&Pbuf[(m0 + g) * AST + pc]     = make_float2(sacc[nt][0], sacc[nt][1]);
            *(float2*)&Pbuf[(m0 + g + 8) * AST + pc] = make_float2(sacc[nt][2], sacc[nt][3]);
            oacc[nt][0] *= sc0; oacc[nt][1] *= sc0;
            oacc[nt][2] *= sc1; oacc[nt][3] *= sc1;
        }
        __syncthreads();   // (D) P fully written, sums ready

        li0 = li0 * sc0 + sumbuf[m0 + g] + sumbuf[64 + m0 + g];
        li1 = li1 * sc1 + sumbuf[m0 + g + 8] + sumbuf[64 + m0 + g + 8];

        // ---- O += P V (split P and V at load) ----
#pragma unroll
        for (int k8 = 0; k8 < 8; k8++) {
            const int kb = k8 * 8;
            uint32_t ph0, ph1, ph2, ph3, pl0, pl1, pl2, pl3;
            split2(Pbuf[(m0 + g) * AST + kb + tig],         ph0, pl0);
            split2(Pbuf[(m0 + g + 8) * AST + kb + tig],     ph1, pl1);
            split2(Pbuf[(m0 + g) * AST + kb + tig + 4],     ph2, pl2);
            split2(Pbuf[(m0 + g + 8) * AST + kb + tig + 4], ph3, pl3);
#pragma unroll
            for (int nt = 0; nt < 4; nt++) {
                const int cn = nb + nt * 8 + g;
                uint32_t vh0, vl0, vh1, vl1;
                split2(Vs[(kb + tig) * AST + cn],     vh0, vl0);
                split2(Vs[(kb + tig + 4) * AST + cn], vh1, vl1);
                mma_tf32(oacc[nt][0], oacc[nt][1], oacc[nt][2], oacc[nt][3],
                         ph0, ph1, ph2, ph3, vh0, vh1);
                mma_tf32(oacc[nt][0], oacc[nt][1], oacc[nt][2], oacc[nt][3],
                         ph0, ph1, ph2, ph3, vl0, vl1);
                mma_tf32(oacc[nt][0], oacc[nt][1], oacc[nt][2], oacc[nt][3],
                         pl0, pl1, pl2, pl3, vh0, vh1);
            }
        }
    }

    // Epilogue: normalize, store head-concat layout
    float* Ob = O + (size_t)b * L_ * D_ + h * HD_;
    const float inv0 = 1.0f / li0;
    const float inv1 = 1.0f / li1;
#pragma unroll
    for (int nt = 0; nt < 4; nt++) {
        const int col = nb + nt * 8 + 2 * tig;
        *(float2*)(Ob + (size_t)(q0 + m0 + g) * D_ + col) =
            make_float2(oacc[nt][0] * inv0, oacc[nt][1] * inv0);
        *(float2*)(Ob + (size_t)(q0 + m0 + g + 8) * D_ + col) =
            make_float2(oacc[nt][2] * inv1, oacc[nt][3] * inv1);
    }
}

// ---------------------------------------------------------------------------
// Launch
// ---------------------------------------------------------------------------
extern "C" void kernel_launch(void* const* d_in, const int* in_sizes, int n_in,
                              void* d_out, int out_size)
{
    (void)in_sizes; (void)n_in; (void)out_size;
    const float* query = (const float*)d_in[0];
    const float* key   = (const float*)d_in[1];
    const float* value = (const float*)d_in[2];
    const float* Wq    = (const float*)d_in[3];
    const float* bq    = (const float*)d_in[4];
    const float* Wk    = (const float*)d_in[5];
    const float* bk    = (const float*)d_in[6];
    const float* Wv    = (const float*)d_in[7];
    const float* bv    = (const float*)d_in[8];
    const float* Wo    = (const float*)d_in[9];
    const float* bo    = (const float*)d_in[10];
    float* out = (float*)d_out;

    float *Qb, *Kb, *Vb, *Cb;
    cudaGetSymbolAddress((void**)&Qb, g_Q);
    cudaGetSymbolAddress((void**)&Kb, g_K);
    cudaGetSymbolAddress((void**)&Vb, g_V);
    cudaGetSymbolAddress((void**)&Cb, g_C);

    const int gemm_smem = 4 * GBUF * 4;            // 40960 bytes
    cudaFuncSetAttribute(gemm_tf32s_bias,
                         cudaFuncAttributeMaxDynamicSharedMemorySize, gemm_smem);
    const int attn_smem = (3 * ATILE + 256) * 4;   // 53248 bytes
    cudaFuncSetAttribute(attn_tc,
                         cudaFuncAttributeMaxDynamicSharedMemorySize, attn_smem);

    dim3 gemm_grid(D_ / 128, M_TOT / 128);  // (8, 64)
    gemm_tf32s_bias<<<gemm_grid, 256, gemm_smem>>>(query, Wq, bq, Qb, M_TOT, D_, D_);
    gemm_tf32s_bias<<<gemm_grid, 256, gemm_smem>>>(key,   Wk, bk, Kb, M_TOT, D_, D_);
    gemm_tf32s_bias<<<gemm_grid, 256, gemm_smem>>>(value, Wv, bv, Vb, M_TOT, D_, D_);

    attn_tc<<<dim3(L_ / 64, B_ * H_), 256, attn_smem>>>(Qb, Kb, Vb, Cb);

    gemm_tf32s_bias<<<gemm_grid, 256, gemm_smem>>>(Cb, Wo, bo, out, M_TOT, D_, D_);
}